// round 1
// baseline (speedup 1.0000x reference)
#include <cuda_runtime.h>

#define BATCH  4
#define NSEQ   2048
#define DMODEL 1024
#define NH     16
#define DKH    64
#define BH     (BATCH*NH)

// Scratch (device globals: allocation-free per harness rules)
__device__ float g_qh[(size_t)BH * NSEQ * DKH];   // [B,H,N,dk]
__device__ float g_kh[(size_t)BH * NSEQ * DKH];
__device__ float g_vh[(size_t)BH * NSEQ * DKH];
__device__ float g_o [(size_t)BATCH * NSEQ * DMODEL]; // [B,N,H*dv]

// ---------------------------------------------------------------------------
// Projection GEMM: qh[b,h,n,k] = sum_d q[b,n,d] * w[h,d,k]
// M=8192 (b*N+n), Ncol=1024 (h*64+k), K=1024. 128x128x8 tile, 8x8 micro.
// gridDim.z selects q/k/v.
// ---------------------------------------------------------------------------
__global__ __launch_bounds__(256) void proj_gemm(
    const float* __restrict__ qin, const float* __restrict__ kin,
    const float* __restrict__ vin,
    const float* __restrict__ wq,  const float* __restrict__ wk,
    const float* __restrict__ wv)
{
    const float* A; const float* W; float* C;
    if (blockIdx.z == 0)      { A = qin; W = wq; C = g_qh; }
    else if (blockIdx.z == 1) { A = kin; W = wk; C = g_kh; }
    else                      { A = vin; W = wv; C = g_vh; }

    __shared__ float As[8][132];   // [k][m] transposed, pad 4 -> conflict-free
    __shared__ float Bs[8][128];   // [k][n]

    const int tid  = threadIdx.x;
    const int row0 = blockIdx.x * 128;
    const int col0 = blockIdx.y * 128;
    const int ty = tid >> 4, tx = tid & 15;

    const int arow = tid >> 1;
    const int acg  = (tid & 1) * 4;
    const int brow = tid >> 5;
    const int bcol = (tid & 31) * 4;

    const int   c     = col0 + bcol;
    const float* wbase = W + (size_t)(c >> 6) * (DMODEL * DKH) + (c & 63);
    const float* abase = A + (size_t)(row0 + arow) * DMODEL + acg;

    float acc[8][8];
    #pragma unroll
    for (int i = 0; i < 8; i++)
        #pragma unroll
        for (int j = 0; j < 8; j++) acc[i][j] = 0.f;

    for (int k0 = 0; k0 < DMODEL; k0 += 8) {
        float4 av = *(const float4*)(abase + k0);
        float4 bv = *(const float4*)(wbase + (size_t)(k0 + brow) * DKH);
        __syncthreads();
        As[acg + 0][arow] = av.x;
        As[acg + 1][arow] = av.y;
        As[acg + 2][arow] = av.z;
        As[acg + 3][arow] = av.w;
        *(float4*)&Bs[brow][bcol] = bv;
        __syncthreads();
        #pragma unroll
        for (int kk = 0; kk < 8; kk++) {
            float a[8], b[8];
            *(float4*)&a[0] = *(const float4*)&As[kk][ty * 8];
            *(float4*)&a[4] = *(const float4*)&As[kk][ty * 8 + 4];
            *(float4*)&b[0] = *(const float4*)&Bs[kk][tx * 8];
            *(float4*)&b[4] = *(const float4*)&Bs[kk][tx * 8 + 4];
            #pragma unroll
            for (int i = 0; i < 8; i++)
                #pragma unroll
                for (int j = 0; j < 8; j++) acc[i][j] += a[i] * b[j];
        }
    }

    #pragma unroll
    for (int i = 0; i < 8; i++) {
        const int r  = row0 + ty * 8 + i;
        const int bb = r >> 11;
        const int n  = r & (NSEQ - 1);
        #pragma unroll
        for (int jc = 0; jc < 8; jc += 4) {
            const int cc = col0 + tx * 8 + jc;
            const int h  = cc >> 6;
            const int kk = cc & 63;
            float4 v4 = make_float4(acc[i][jc], acc[i][jc+1], acc[i][jc+2], acc[i][jc+3]);
            *(float4*)&C[(((size_t)bb * NH + h) * NSEQ + n) * DKH + kk] = v4;
        }
    }
}

// ---------------------------------------------------------------------------
// Causal flash attention, fp32. One CTA = one (b,h) x 64-query block.
// 64x64 tiles, 256 threads, 4x4 micro-tile. P aliases the K smem buffer.
// ---------------------------------------------------------------------------
__global__ void __launch_bounds__(256, 2) flash_attn()
{
    extern __shared__ float sm[];
    float* Qs = sm;                 // [64][64]
    float* Ks = sm + 64 * 64;       // [64][68]  (also reused as Ps [64][68])
    float* Vs = Ks + 64 * 68;       // [64][64]
    float* Ps = Ks;

    const int tid = threadIdx.x;
    const int ty = tid >> 4, tx = tid & 15;
    const int r0 = ty * 4, c0 = tx * 4;
    const int qb = blockIdx.x, bh = blockIdx.y;
    const int q0 = qb * 64;
    const size_t base = (size_t)bh * NSEQ * DKH;

    #pragma unroll
    for (int it = 0; it < 4; it++) {
        int s = tid + it * 256;
        int row = s >> 4, d4 = (s & 15) * 4;
        *(float4*)&Qs[row * 64 + d4] =
            *(const float4*)&g_qh[base + (size_t)(q0 + row) * DKH + d4];
    }

    float O[4][4];
    float m[4], l[4];
    #pragma unroll
    for (int i = 0; i < 4; i++) {
        m[i] = -1e30f; l[i] = 0.f;
        #pragma unroll
        for (int j = 0; j < 4; j++) O[i][j] = 0.f;
    }

    for (int j = 0; j <= qb; j++) {
        const int k0 = j * 64;
        __syncthreads();   // prior-iter P/V reads done before overwrite
        #pragma unroll
        for (int it = 0; it < 4; it++) {
            int s = tid + it * 256;
            int row = s >> 4, d4 = (s & 15) * 4;
            *(float4*)&Ks[row * 68 + d4] =
                *(const float4*)&g_kh[base + (size_t)(k0 + row) * DKH + d4];
            *(float4*)&Vs[row * 64 + d4] =
                *(const float4*)&g_vh[base + (size_t)(k0 + row) * DKH + d4];
        }
        __syncthreads();

        float S[4][4];
        #pragma unroll
        for (int i = 0; i < 4; i++)
            #pragma unroll
            for (int jj = 0; jj < 4; jj++) S[i][jj] = 0.f;

        #pragma unroll
        for (int d = 0; d < 64; d += 4) {
            float4 qv[4], kv[4];
            #pragma unroll
            for (int i = 0; i < 4; i++)
                qv[i] = *(const float4*)&Qs[(r0 + i) * 64 + d];
            #pragma unroll
            for (int jj = 0; jj < 4; jj++)
                kv[jj] = *(const float4*)&Ks[(c0 + jj) * 68 + d];
            #pragma unroll
            for (int i = 0; i < 4; i++)
                #pragma unroll
                for (int jj = 0; jj < 4; jj++) {
                    S[i][jj] += qv[i].x * kv[jj].x;
                    S[i][jj] += qv[i].y * kv[jj].y;
                    S[i][jj] += qv[i].z * kv[jj].z;
                    S[i][jj] += qv[i].w * kv[jj].w;
                }
        }

        float p[4][4];
        const bool diag = (j == qb);
        #pragma unroll
        for (int i = 0; i < 4; i++) {
            #pragma unroll
            for (int jj = 0; jj < 4; jj++) {
                float t = S[i][jj] * 0.125f;          // 1/sqrt(64)
                if (diag && (c0 + jj > r0 + i)) t = -1e30f;
                p[i][jj] = t;
            }
            float rm = fmaxf(fmaxf(p[i][0], p[i][1]), fmaxf(p[i][2], p[i][3]));
            rm = fmaxf(rm, __shfl_xor_sync(0xffffffffu, rm, 1));
            rm = fmaxf(rm, __shfl_xor_sync(0xffffffffu, rm, 2));
            rm = fmaxf(rm, __shfl_xor_sync(0xffffffffu, rm, 4));
            rm = fmaxf(rm, __shfl_xor_sync(0xffffffffu, rm, 8));
            float mn = fmaxf(m[i], rm);
            float alpha = __expf(m[i] - mn);
            m[i] = mn;
            float rs = 0.f;
            #pragma unroll
            for (int jj = 0; jj < 4; jj++) {
                float e = __expf(p[i][jj] - mn);
                p[i][jj] = e;
                rs += e;
            }
            rs += __shfl_xor_sync(0xffffffffu, rs, 1);
            rs += __shfl_xor_sync(0xffffffffu, rs, 2);
            rs += __shfl_xor_sync(0xffffffffu, rs, 4);
            rs += __shfl_xor_sync(0xffffffffu, rs, 8);
            l[i] = l[i] * alpha + rs;
            #pragma unroll
            for (int jj = 0; jj < 4; jj++) O[i][jj] *= alpha;
        }

        __syncthreads();   // everyone finished reading Ks before aliasing as Ps
        #pragma unroll
        for (int i = 0; i < 4; i++)
            *(float4*)&Ps[(r0 + i) * 68 + c0] =
                make_float4(p[i][0], p[i][1], p[i][2], p[i][3]);
        __syncthreads();

        #pragma unroll 8
        for (int cc = 0; cc < 64; cc++) {
            float4 vv = *(const float4*)&Vs[cc * 64 + c0];
            float a0 = Ps[(r0 + 0) * 68 + cc];
            float a1 = Ps[(r0 + 1) * 68 + cc];
            float a2 = Ps[(r0 + 2) * 68 + cc];
            float a3 = Ps[(r0 + 3) * 68 + cc];
            O[0][0] += a0 * vv.x; O[0][1] += a0 * vv.y; O[0][2] += a0 * vv.z; O[0][3] += a0 * vv.w;
            O[1][0] += a1 * vv.x; O[1][1] += a1 * vv.y; O[1][2] += a1 * vv.z; O[1][3] += a1 * vv.w;
            O[2][0] += a2 * vv.x; O[2][1] += a2 * vv.y; O[2][2] += a2 * vv.z; O[2][3] += a2 * vv.w;
            O[3][0] += a3 * vv.x; O[3][1] += a3 * vv.y; O[3][2] += a3 * vv.z; O[3][3] += a3 * vv.w;
        }
    }

    const int bb = bh >> 4, h = bh & 15;
    #pragma unroll
    for (int i = 0; i < 4; i++) {
        const float inv = 1.f / l[i];
        const int r = q0 + r0 + i;
        float4 v4 = make_float4(O[i][0]*inv, O[i][1]*inv, O[i][2]*inv, O[i][3]*inv);
        *(float4*)&g_o[((size_t)bb * NSEQ + r) * DMODEL + h * DKH + c0] = v4;
    }
}

// ---------------------------------------------------------------------------
// Output GEMM: out[8192,1024] = g_o[8192,1024] @ w_o[1024,1024] (row-major)
// ---------------------------------------------------------------------------
__global__ __launch_bounds__(256) void out_gemm(
    const float* __restrict__ W, float* __restrict__ out)
{
    __shared__ float As[8][132];
    __shared__ float Bs[8][128];

    const int tid  = threadIdx.x;
    const int row0 = blockIdx.x * 128;
    const int col0 = blockIdx.y * 128;
    const int ty = tid >> 4, tx = tid & 15;

    const int arow = tid >> 1;
    const int acg  = (tid & 1) * 4;
    const int brow = tid >> 5;
    const int bcol = (tid & 31) * 4;

    const float* abase = g_o + (size_t)(row0 + arow) * DMODEL + acg;
    const float* wbase = W + col0 + bcol;

    float acc[8][8];
    #pragma unroll
    for (int i = 0; i < 8; i++)
        #pragma unroll
        for (int j = 0; j < 8; j++) acc[i][j] = 0.f;

    for (int k0 = 0; k0 < DMODEL; k0 += 8) {
        float4 av = *(const float4*)(abase + k0);
        float4 bv = *(const float4*)(wbase + (size_t)(k0 + brow) * DMODEL);
        __syncthreads();
        As[acg + 0][arow] = av.x;
        As[acg + 1][arow] = av.y;
        As[acg + 2][arow] = av.z;
        As[acg + 3][arow] = av.w;
        *(float4*)&Bs[brow][bcol] = bv;
        __syncthreads();
        #pragma unroll
        for (int kk = 0; kk < 8; kk++) {
            float a[8], b[8];
            *(float4*)&a[0] = *(const float4*)&As[kk][ty * 8];
            *(float4*)&a[4] = *(const float4*)&As[kk][ty * 8 + 4];
            *(float4*)&b[0] = *(const float4*)&Bs[kk][tx * 8];
            *(float4*)&b[4] = *(const float4*)&Bs[kk][tx * 8 + 4];
            #pragma unroll
            for (int i = 0; i < 8; i++)
                #pragma unroll
                for (int j = 0; j < 8; j++) acc[i][j] += a[i] * b[j];
        }
    }

    #pragma unroll
    for (int i = 0; i < 8; i++) {
        const int r = row0 + ty * 8 + i;
        #pragma unroll
        for (int jc = 0; jc < 8; jc += 4) {
            const int cc = col0 + tx * 8 + jc;
            float4 v4 = make_float4(acc[i][jc], acc[i][jc+1], acc[i][jc+2], acc[i][jc+3]);
            *(float4*)&out[(size_t)r * DMODEL + cc] = v4;
        }
    }
}

// ---------------------------------------------------------------------------
extern "C" void kernel_launch(void* const* d_in, const int* in_sizes, int n_in,
                              void* d_out, int out_size)
{
    (void)in_sizes; (void)n_in; (void)out_size;
    const float* q   = (const float*)d_in[0];
    const float* k   = (const float*)d_in[1];
    const float* v   = (const float*)d_in[2];
    const float* w_q = (const float*)d_in[3];
    const float* w_k = (const float*)d_in[4];
    const float* w_v = (const float*)d_in[5];
    const float* w_o = (const float*)d_in[6];
    float* out = (float*)d_out;

    const int flash_smem = (64*64 + 64*68 + 64*64) * (int)sizeof(float); // 50176
    cudaFuncSetAttribute(flash_attn, cudaFuncAttributeMaxDynamicSharedMemorySize,
                         flash_smem);

    dim3 gproj(8192 / 128, 1024 / 128, 3);
    proj_gemm<<<gproj, 256>>>(q, k, v, w_q, w_k, w_v);

    dim3 gflash(NSEQ / 64, BH);
    flash_attn<<<gflash, 256, flash_smem>>>();

    dim3 gout(8192 / 128, 1024 / 128);
    out_gemm<<<gout, 256>>>(w_o, out);
}